// round 5
// baseline (speedup 1.0000x reference)
#include <cuda_runtime.h>
#include <cuda_fp16.h>
#include <cstdint>

// out = x @ (Wv@Wo) + (bv@Wo + bo)   (algebraic collapse, validated r1)
// fp16 2-pass GEMM: out ≈ x_h @ (Whi + Wlo).  rel_err ~2^-12 (measured 2.1e-4).

#define D 512
#define MTOK 16384

__device__ __half g_Ahi[MTOK * D];
__device__ __half g_Bhi[D * D];   // WcT hi  [n][k]
__device__ __half g_Blo[D * D];   // WcT lo  [n][k]
__device__ float g_bc[D];

// ───────────────────────── helpers ─────────────────────────
__device__ __forceinline__ uint32_t smem_u32(const void* p) {
    uint32_t a;
    asm("{ .reg .u64 t; cvta.to.shared.u64 t, %1; cvt.u32.u64 %0, t; }"
        : "=r"(a) : "l"(p));
    return a;
}
__device__ __forceinline__ void cp16(uint32_t dst, const void* src) {
    asm volatile("cp.async.cg.shared.global [%0], [%1], 16;"
                 :: "r"(dst), "l"(src) : "memory");
}
__device__ __forceinline__ void cp_commit() {
    asm volatile("cp.async.commit_group;" ::: "memory");
}
template <int N>
__device__ __forceinline__ void cp_wait() {
    asm volatile("cp.async.wait_group %0;" :: "n"(N) : "memory");
}
__device__ __forceinline__ void ldsm_x4(uint32_t (&r)[4], uint32_t addr) {
    asm volatile("ldmatrix.sync.aligned.m8n8.x4.shared.b16 {%0,%1,%2,%3}, [%4];"
                 : "=r"(r[0]), "=r"(r[1]), "=r"(r[2]), "=r"(r[3]) : "r"(addr));
}
__device__ __forceinline__ void mma_f16(float (&d)[4], const uint32_t (&a)[4],
                                        uint32_t b0, uint32_t b1) {
    asm volatile(
        "mma.sync.aligned.m16n8k16.row.col.f32.f16.f16.f32 "
        "{%0,%1,%2,%3}, {%4,%5,%6,%7}, {%8,%9}, {%0,%1,%2,%3};"
        : "+f"(d[0]), "+f"(d[1]), "+f"(d[2]), "+f"(d[3])
        : "r"(a[0]), "r"(a[1]), "r"(a[2]), "r"(a[3]), "r"(b0), "r"(b1));
}

// ───────────── fused pre-kernel: convert | combine | bc by block role ─────────────
// blocks [0, nConv):            x -> fp16  (2048 elems/block)
// blocks [nConv, nConv+256):    Wc = Wv@Wo (32x32 tile), store WcT hi/lo fp16
// blocks [nConv+256, +512):     bc[n] = bv @ Wo[:,n] + bo[n]
__global__ __launch_bounds__(256)
void pre_kernel(const float* __restrict__ x,
                const float* __restrict__ Wv, const float* __restrict__ Wo,
                const float* __restrict__ bv, const float* __restrict__ bo,
                int nConv)
{
    const int b = blockIdx.x;
    const int tid = threadIdx.x;

    if (b < nConv) {
        // ---- convert role ----
        size_t i = ((size_t)b * 256 + tid) * 8;
        float4 v0 = *reinterpret_cast<const float4*>(x + i);
        float4 v1 = *reinterpret_cast<const float4*>(x + i + 4);
        __half2 h[4];
        h[0] = __floats2half2_rn(v0.x, v0.y);
        h[1] = __floats2half2_rn(v0.z, v0.w);
        h[2] = __floats2half2_rn(v1.x, v1.y);
        h[3] = __floats2half2_rn(v1.z, v1.w);
        *reinterpret_cast<uint4*>(&g_Ahi[i]) = *reinterpret_cast<uint4*>(h);
        return;
    }

    if (b < nConv + 256) {
        // ---- combine role ----
        __shared__ float As[32][33];   // As[k][m]
        __shared__ float Bs[32][33];   // Bs[k][n]
        const int bid = b - nConv;
        const int kb0 = (bid >> 4) * 32;   // Wc row (k)
        const int nb0 = (bid & 15) * 32;   // Wc col (n)
        const int ty = (tid >> 4) * 2;
        const int tx = (tid & 15) * 2;

        float acc[2][2] = {};
        for (int k0 = 0; k0 < D; k0 += 32) {
            const int r = tid >> 3, c = (tid & 7) * 4;
            float4 va = *reinterpret_cast<const float4*>(&Wv[(size_t)(kb0 + r) * D + k0 + c]);
            As[c + 0][r] = va.x; As[c + 1][r] = va.y;
            As[c + 2][r] = va.z; As[c + 3][r] = va.w;
            float4 vb = *reinterpret_cast<const float4*>(&Wo[(size_t)(k0 + r) * D + nb0 + c]);
            Bs[r][c + 0] = vb.x; Bs[r][c + 1] = vb.y;
            Bs[r][c + 2] = vb.z; Bs[r][c + 3] = vb.w;
            __syncthreads();
            #pragma unroll
            for (int k = 0; k < 32; k++) {
                float a0 = As[k][ty], a1 = As[k][ty + 1];
                float b0 = Bs[k][tx], b1 = Bs[k][tx + 1];
                acc[0][0] += a0 * b0; acc[0][1] += a0 * b1;
                acc[1][0] += a1 * b0; acc[1][1] += a1 * b1;
            }
            __syncthreads();
        }
        #pragma unroll
        for (int i = 0; i < 2; i++)
            #pragma unroll
            for (int j = 0; j < 2; j++) {
                float w = acc[i][j];
                int k = kb0 + ty + i;
                int n = nb0 + tx + j;
                __half h = __float2half_rn(w);
                __half l = __float2half_rn(w - __half2float(h));
                g_Bhi[(size_t)n * D + k] = h;
                g_Blo[(size_t)n * D + k] = l;
            }
        return;
    }

    // ---- bc role ----
    {
        __shared__ float red[8];
        const int n = b - nConv - 256;
        float s = 0.f;
        #pragma unroll
        for (int j = tid; j < D; j += 256) s += bv[j] * Wo[(size_t)j * D + n];
        #pragma unroll
        for (int o = 16; o > 0; o >>= 1) s += __shfl_down_sync(0xFFFFFFFF, s, o);
        if ((tid & 31) == 0) red[tid >> 5] = s;
        __syncthreads();
        if (tid == 0) {
            float t = 0.f;
            #pragma unroll
            for (int w = 0; w < 8; w++) t += red[w];
            g_bc[n] = t + bo[n];
        }
    }
}

// ───────────── main GEMM via mma.sync fp16 2-pass ─────────────
// CTA 128x128, BK=32, 3-stage cp.async, 2 CTAs/SM. 8 warps, warp tile 64x32.
#define BM 128
#define BN 128
#define BKK 32
#define ROWB 80                       // smem row stride bytes (40 fp16)
#define TILE_B (128 * ROWB)           // 10240 B per operand tile
#define STAGE_B (3 * TILE_B)          // Ahi, Bhi, Blo
#define NSTAGE 3
#define SMEM_TOTAL (NSTAGE * STAGE_B) // 92160 B

__global__ __launch_bounds__(256, 2)
void mma_kernel(const __half* __restrict__ Ahi,
                const __half* __restrict__ Bhi, const __half* __restrict__ Blo,
                const float* __restrict__ bc, float* __restrict__ out)
{
    extern __shared__ char smem[];
    const uint32_t sb = smem_u32(smem);
    const int tid = threadIdx.x;
    const int lane = tid & 31;
    const int wid = tid >> 5;
    const int m0 = blockIdx.x * BM;
    const int n0 = blockIdx.y * BN;
    const int wm = (wid >> 2) * 64;
    const int wn = (wid & 3) * 32;

    auto load_stage = [&](int kb, int s) {
        const uint32_t base = sb + (uint32_t)s * STAGE_B;
        const int k0 = kb * BKK;
        #pragma unroll
        for (int u = 0; u < 2; u++) {
            const int ch = tid + u * 256;        // 0..511
            const int r = ch >> 2, c = ch & 3;   // 128 rows x 4 16B-chunks
            const uint32_t soff = r * ROWB + c * 16;
            const size_t ga = (size_t)(m0 + r) * D + k0 + c * 8;
            const size_t gb = (size_t)(n0 + r) * D + k0 + c * 8;
            cp16(base + 0 * TILE_B + soff, Ahi + ga);
            cp16(base + 1 * TILE_B + soff, Bhi + gb);
            cp16(base + 2 * TILE_B + soff, Blo + gb);
        }
    };

    float acc[4][4][4] = {};

    load_stage(0, 0); cp_commit();
    load_stage(1, 1); cp_commit();
    load_stage(2, 2); cp_commit();

    const int NKB = D / BKK;   // 16
    int stage = 0;
    for (int kb = 0; kb < NKB; kb++) {
        if (kb <= NKB - 3)      cp_wait<2>();
        else if (kb == NKB - 2) cp_wait<1>();
        else                    cp_wait<0>();
        __syncthreads();

        const uint32_t base = sb + (uint32_t)stage * STAGE_B;
        #pragma unroll
        for (int ks = 0; ks < 2; ks++) {
            uint32_t a[4][4];
            #pragma unroll
            for (int mi = 0; mi < 4; mi++) {
                uint32_t ra = base + (uint32_t)(wm + mi * 16 + (lane & 15)) * ROWB
                            + ks * 32 + ((lane >> 4) << 4);
                ldsm_x4(a[mi], ra);
            }
            uint32_t bh[2][4], bl[2][4];
            #pragma unroll
            for (int bi = 0; bi < 2; bi++) {
                const int nl = wn + bi * 16 + (lane & 7) + ((lane >> 4) << 3);
                uint32_t rb = base + TILE_B + (uint32_t)nl * ROWB
                            + ks * 32 + (((lane >> 3) & 1) << 4);
                ldsm_x4(bh[bi], rb);
                ldsm_x4(bl[bi], rb + TILE_B);
            }
            #pragma unroll
            for (int mi = 0; mi < 4; mi++)
                #pragma unroll
                for (int ni = 0; ni < 4; ni++) {
                    const int bi = ni >> 1, p = (ni & 1) * 2;
                    mma_f16(acc[mi][ni], a[mi], bh[bi][p], bh[bi][p + 1]);
                    mma_f16(acc[mi][ni], a[mi], bl[bi][p], bl[bi][p + 1]);
                }
        }
        __syncthreads();

        if (kb + NSTAGE < NKB) { load_stage(kb + NSTAGE, stage); cp_commit(); }
        stage = (stage == NSTAGE - 1) ? 0 : stage + 1;
    }

    // epilogue: fp32 stores + bias
    #pragma unroll
    for (int mi = 0; mi < 4; mi++) {
        const int r = m0 + wm + mi * 16 + (lane >> 2);
        #pragma unroll
        for (int ni = 0; ni < 4; ni++) {
            const int c = n0 + wn + ni * 8 + (lane & 3) * 2;
            float2 bv = *reinterpret_cast<const float2*>(&bc[c]);
            float2 v0 = make_float2(acc[mi][ni][0] + bv.x, acc[mi][ni][1] + bv.y);
            float2 v1 = make_float2(acc[mi][ni][2] + bv.x, acc[mi][ni][3] + bv.y);
            *reinterpret_cast<float2*>(&out[(size_t)r * D + c]) = v0;
            *reinterpret_cast<float2*>(&out[(size_t)(r + 8) * D + c]) = v1;
        }
    }
}

// ───────────────────────── host ─────────────────────────
extern "C" void kernel_launch(void* const* d_in, const int* in_sizes, int n_in,
                              void* d_out, int out_size)
{
    // order: x, H, W, Wq, bq, Wk, bk, Wv, bv, Wo, bo, Woff1, boff1, Woff2, boff2
    const float* x  = (const float*)d_in[0];
    const float* Wv = (const float*)d_in[7];
    const float* bv = (const float*)d_in[8];
    const float* Wo = (const float*)d_in[9];
    const float* bo = (const float*)d_in[10];
    float* out = (float*)d_out;

    const int M = in_sizes[0] / D;   // 16384 tokens

    __half *ahi, *bhi, *blo;
    float* bc;
    cudaGetSymbolAddress((void**)&ahi, g_Ahi);
    cudaGetSymbolAddress((void**)&bhi, g_Bhi);
    cudaGetSymbolAddress((void**)&blo, g_Blo);
    cudaGetSymbolAddress((void**)&bc,  g_bc);

    static bool attr_set = false;
    if (!attr_set) {
        cudaFuncSetAttribute(mma_kernel,
                             cudaFuncAttributeMaxDynamicSharedMemorySize, SMEM_TOTAL);
        attr_set = true;
    }

    const int nConv = (M * D) / (256 * 8);           // 4096
    pre_kernel<<<nConv + 256 + D, 256>>>(x, Wv, Wo, bv, bo, nConv);
    mma_kernel<<<dim3(M / BM, D / BN), 256, SMEM_TOTAL>>>(ahi, bhi, blo, bc, out);
}

// round 6
// speedup vs baseline: 1.5439x; 1.5439x over previous
#include <cuda_runtime.h>
#include <cuda_fp16.h>
#include <cstdint>

// out = x @ (Wv@Wo) + (bv@Wo + bo)   (algebraic collapse, validated r1)
// Single-pass fp16 GEMM with inline fp32->fp16 A conversion (no convert pass).
// Expected rel_err ~3-4e-4 (x-quant 2.08e-4 measured + W-quant ~2e-4).

#define D 512

__device__ __half g_Bhi[D * D];   // WcT fp16  [n][k]
__device__ float g_bc[D];

// ───────────────────────── helpers ─────────────────────────
__device__ __forceinline__ uint32_t smem_u32(const void* p) {
    uint32_t a;
    asm("{ .reg .u64 t; cvta.to.shared.u64 t, %1; cvt.u32.u64 %0, t; }"
        : "=r"(a) : "l"(p));
    return a;
}
__device__ __forceinline__ void cp16(uint32_t dst, const void* src) {
    asm volatile("cp.async.cg.shared.global [%0], [%1], 16;"
                 :: "r"(dst), "l"(src) : "memory");
}
__device__ __forceinline__ void cp_commit() {
    asm volatile("cp.async.commit_group;" ::: "memory");
}
template <int N>
__device__ __forceinline__ void cp_wait() {
    asm volatile("cp.async.wait_group %0;" :: "n"(N) : "memory");
}
__device__ __forceinline__ void ldsm_x4(uint32_t (&r)[4], uint32_t addr) {
    asm volatile("ldmatrix.sync.aligned.m8n8.x4.shared.b16 {%0,%1,%2,%3}, [%4];"
                 : "=r"(r[0]), "=r"(r[1]), "=r"(r[2]), "=r"(r[3]) : "r"(addr));
}
__device__ __forceinline__ void mma_f16(float (&d)[4], const uint32_t (&a)[4],
                                        uint32_t b0, uint32_t b1) {
    asm volatile(
        "mma.sync.aligned.m16n8k16.row.col.f32.f16.f16.f32 "
        "{%0,%1,%2,%3}, {%4,%5,%6,%7}, {%8,%9}, {%0,%1,%2,%3};"
        : "+f"(d[0]), "+f"(d[1]), "+f"(d[2]), "+f"(d[3])
        : "r"(a[0]), "r"(a[1]), "r"(a[2]), "r"(a[3]), "r"(b0), "r"(b1));
}

// ───────────── pre-kernel: combine | bc by block role ─────────────
// blocks [0,256):   Wc = Wv@Wo (32x32 tile), store WcT fp16
// blocks [256,768): bc[n] = bv @ Wo[:,n] + bo[n]
__global__ __launch_bounds__(256)
void pre_kernel(const float* __restrict__ Wv, const float* __restrict__ Wo,
                const float* __restrict__ bv, const float* __restrict__ bo)
{
    const int b = blockIdx.x;
    const int tid = threadIdx.x;

    if (b < 256) {
        __shared__ float As[32][33];   // As[k][m]
        __shared__ float Bs[32][33];   // Bs[k][n]
        const int kb0 = (b >> 4) * 32;   // Wc row (k)
        const int nb0 = (b & 15) * 32;   // Wc col (n)
        const int ty = (tid >> 4) * 2;
        const int tx = (tid & 15) * 2;

        float acc[2][2] = {};
        for (int k0 = 0; k0 < D; k0 += 32) {
            const int r = tid >> 3, c = (tid & 7) * 4;
            float4 va = *reinterpret_cast<const float4*>(&Wv[(size_t)(kb0 + r) * D + k0 + c]);
            As[c + 0][r] = va.x; As[c + 1][r] = va.y;
            As[c + 2][r] = va.z; As[c + 3][r] = va.w;
            float4 vb = *reinterpret_cast<const float4*>(&Wo[(size_t)(k0 + r) * D + nb0 + c]);
            Bs[r][c + 0] = vb.x; Bs[r][c + 1] = vb.y;
            Bs[r][c + 2] = vb.z; Bs[r][c + 3] = vb.w;
            __syncthreads();
            #pragma unroll
            for (int k = 0; k < 32; k++) {
                float a0 = As[k][ty], a1 = As[k][ty + 1];
                float b0 = Bs[k][tx], b1 = Bs[k][tx + 1];
                acc[0][0] += a0 * b0; acc[0][1] += a0 * b1;
                acc[1][0] += a1 * b0; acc[1][1] += a1 * b1;
            }
            __syncthreads();
        }
        #pragma unroll
        for (int i = 0; i < 2; i++)
            #pragma unroll
            for (int j = 0; j < 2; j++) {
                int k = kb0 + ty + i;
                int n = nb0 + tx + j;
                g_Bhi[(size_t)n * D + k] = __float2half_rn(acc[i][j]);
            }
        return;
    }

    // bc role
    {
        __shared__ float red[8];
        const int n = b - 256;
        float s = 0.f;
        #pragma unroll
        for (int j = tid; j < D; j += 256) s += bv[j] * Wo[(size_t)j * D + n];
        #pragma unroll
        for (int o = 16; o > 0; o >>= 1) s += __shfl_down_sync(0xFFFFFFFF, s, o);
        if ((tid & 31) == 0) red[tid >> 5] = s;
        __syncthreads();
        if (tid == 0) {
            float t = 0.f;
            #pragma unroll
            for (int w = 0; w < 8; w++) t += red[w];
            g_bc[n] = t + bo[n];
        }
    }
}

// ───────────── main GEMM: fp32 A inline-converted, fp16 mma.sync ─────────────
// CTA 128x128, BK=32, 2-stage: A via LDG->cvt->STS register double-buffer,
// B via cp.async. 8 warps, warp tile 64x32. 2 CTAs/SM.
#define BM 128
#define BN 128
#define BKK 32
#define ROWB 80                        // smem row stride bytes (32 fp16 + pad)
#define A_TILE (128 * ROWB)            // 10240 B
#define B_TILE (128 * ROWB)            // 10240 B
#define STAGE_B (A_TILE + B_TILE)      // 20480 B
#define SMEM_TOTAL (2 * STAGE_B)       // 40960 B

__global__ __launch_bounds__(256, 2)
void mma_kernel(const float* __restrict__ x,
                const __half* __restrict__ Bhi,
                const float* __restrict__ bc, float* __restrict__ out)
{
    extern __shared__ char smem[];
    const uint32_t sb = smem_u32(smem);
    const int tid = threadIdx.x;
    const int lane = tid & 31;
    const int wid = tid >> 5;
    const int n0 = blockIdx.x * BN;   // n fast: 4 CTAs share an A tile
    const int m0 = blockIdx.y * BM;
    const int wm = (wid >> 2) * 64;
    const int wn = (wid & 3) * 32;

    const int ar = tid >> 3;          // 0..31 (base row)
    const int ac = tid & 7;           // float4 column index (0..7)

    float4 areg[4];

    auto lda = [&](int kb) {
        const int k0 = kb * BKK;
        #pragma unroll
        for (int u = 0; u < 4; u++) {
            const int r = ar + u * 32;
            areg[u] = __ldg(reinterpret_cast<const float4*>(
                &x[(size_t)(m0 + r) * D + k0 + ac * 4]));
        }
    };
    auto sta = [&](int s) {
        char* base = smem + s * STAGE_B;
        #pragma unroll
        for (int u = 0; u < 4; u++) {
            const int r = ar + u * 32;
            __half2 h0 = __floats2half2_rn(areg[u].x, areg[u].y);
            __half2 h1 = __floats2half2_rn(areg[u].z, areg[u].w);
            uint2 v;
            v.x = *reinterpret_cast<uint32_t*>(&h0);
            v.y = *reinterpret_cast<uint32_t*>(&h1);
            *reinterpret_cast<uint2*>(base + r * ROWB + ac * 8) = v;
        }
    };
    auto ldb = [&](int kb, int s) {
        const uint32_t base = sb + (uint32_t)s * STAGE_B + A_TILE;
        const int k0 = kb * BKK;
        #pragma unroll
        for (int u = 0; u < 2; u++) {
            const int ch = tid + u * 256;        // 0..511
            const int r = ch >> 2, c = ch & 3;   // 128 rows x 4 16B-chunks
            cp16(base + r * ROWB + c * 16,
                 Bhi + (size_t)(n0 + r) * D + k0 + c * 8);
        }
    };

    float acc[4][4][4] = {};

    // prologue
    lda(0); sta(0);
    ldb(0, 0); cp_commit();
    lda(1);                    // regs hold A(1)
    ldb(1, 1); cp_commit();

    const int NKB = D / BKK;   // 16
    for (int kb = 0; kb < NKB; kb++) {
        const int b = kb & 1;
        if (kb < NKB - 1) cp_wait<1>(); else cp_wait<0>();
        __syncthreads();

        const uint32_t baseA = sb + (uint32_t)b * STAGE_B;
        const uint32_t baseB = baseA + A_TILE;
        #pragma unroll
        for (int ks = 0; ks < 2; ks++) {
            uint32_t a[4][4];
            #pragma unroll
            for (int mi = 0; mi < 4; mi++) {
                uint32_t ra = baseA + (uint32_t)(wm + mi * 16 + (lane & 15)) * ROWB
                            + ks * 32 + ((lane >> 4) << 4);
                ldsm_x4(a[mi], ra);
            }
            uint32_t bh[2][4];
            #pragma unroll
            for (int bi = 0; bi < 2; bi++) {
                const int nl = wn + bi * 16 + (lane & 7) + ((lane >> 4) << 3);
                uint32_t rb = baseB + (uint32_t)nl * ROWB
                            + ks * 32 + (((lane >> 3) & 1) << 4);
                ldsm_x4(bh[bi], rb);
            }
            #pragma unroll
            for (int mi = 0; mi < 4; mi++)
                #pragma unroll
                for (int ni = 0; ni < 4; ni++) {
                    const int bi = ni >> 1, p = (ni & 1) * 2;
                    mma_f16(acc[mi][ni], a[mi], bh[bi][p], bh[bi][p + 1]);
                }
        }
        __syncthreads();

        if (kb + 1 < NKB) {
            sta(b ^ 1);                 // A(kb+1) -> its stage buffer
            if (kb + 2 < NKB) {
                lda(kb + 2);            // prefetch A(kb+2) into regs
                ldb(kb + 2, b);         // B(kb+2) -> freed buffer
            }
            cp_commit();                // keep group counting uniform
        }
    }

    // epilogue: fp32 stores + bias
    #pragma unroll
    for (int mi = 0; mi < 4; mi++) {
        const int r = m0 + wm + mi * 16 + (lane >> 2);
        #pragma unroll
        for (int ni = 0; ni < 4; ni++) {
            const int c = n0 + wn + ni * 8 + (lane & 3) * 2;
            float2 bv = *reinterpret_cast<const float2*>(&bc[c]);
            float2 v0 = make_float2(acc[mi][ni][0] + bv.x, acc[mi][ni][1] + bv.y);
            float2 v1 = make_float2(acc[mi][ni][2] + bv.x, acc[mi][ni][3] + bv.y);
            *reinterpret_cast<float2*>(&out[(size_t)r * D + c]) = v0;
            *reinterpret_cast<float2*>(&out[(size_t)(r + 8) * D + c]) = v1;
        }
    }
}

// ───────────────────────── host ─────────────────────────
extern "C" void kernel_launch(void* const* d_in, const int* in_sizes, int n_in,
                              void* d_out, int out_size)
{
    // order: x, H, W, Wq, bq, Wk, bk, Wv, bv, Wo, bo, Woff1, boff1, Woff2, boff2
    const float* x  = (const float*)d_in[0];
    const float* Wv = (const float*)d_in[7];
    const float* bv = (const float*)d_in[8];
    const float* Wo = (const float*)d_in[9];
    const float* bo = (const float*)d_in[10];
    float* out = (float*)d_out;

    const int M = in_sizes[0] / D;   // 16384 tokens

    __half* bhi;
    float* bc;
    cudaGetSymbolAddress((void**)&bhi, g_Bhi);
    cudaGetSymbolAddress((void**)&bc,  g_bc);

    static bool attr_set = false;
    if (!attr_set) {
        cudaFuncSetAttribute(mma_kernel,
                             cudaFuncAttributeMaxDynamicSharedMemorySize, SMEM_TOTAL);
        attr_set = true;
    }

    pre_kernel<<<256 + D, 256>>>(Wv, Wo, bv, bo);
    mma_kernel<<<dim3(D / BN, M / BM), 256, SMEM_TOTAL>>>(x, bhi, bc, out);
}

// round 7
// speedup vs baseline: 1.5652x; 1.0138x over previous
#include <cuda_runtime.h>
#include <cuda_fp16.h>
#include <cstdint>

// out = x @ (Wv@Wo) + (bv@Wo + bo)   (algebraic collapse, validated r1)
// Single-pass fp16 GEMM, inline fp32->fp16 A conversion. rel_err ~2.9e-4 measured.

#define D 512

__device__ __half g_Bhi[D * D];   // WcT fp16  [n][k]
__device__ float g_bc[D];

// ───────────────────────── helpers ─────────────────────────
__device__ __forceinline__ uint32_t smem_u32(const void* p) {
    uint32_t a;
    asm("{ .reg .u64 t; cvta.to.shared.u64 t, %1; cvt.u32.u64 %0, t; }"
        : "=r"(a) : "l"(p));
    return a;
}
__device__ __forceinline__ void cp16(uint32_t dst, const void* src) {
    asm volatile("cp.async.cg.shared.global [%0], [%1], 16;"
                 :: "r"(dst), "l"(src) : "memory");
}
__device__ __forceinline__ void cp_commit() {
    asm volatile("cp.async.commit_group;" ::: "memory");
}
template <int N>
__device__ __forceinline__ void cp_wait() {
    asm volatile("cp.async.wait_group %0;" :: "n"(N) : "memory");
}
__device__ __forceinline__ void ldsm_x4(uint32_t (&r)[4], uint32_t addr) {
    asm volatile("ldmatrix.sync.aligned.m8n8.x4.shared.b16 {%0,%1,%2,%3}, [%4];"
                 : "=r"(r[0]), "=r"(r[1]), "=r"(r[2]), "=r"(r[3]) : "r"(addr));
}
__device__ __forceinline__ void mma_f16(float (&d)[4], const uint32_t (&a)[4],
                                        uint32_t b0, uint32_t b1) {
    asm volatile(
        "mma.sync.aligned.m16n8k16.row.col.f32.f16.f16.f32 "
        "{%0,%1,%2,%3}, {%4,%5,%6,%7}, {%8,%9}, {%0,%1,%2,%3};"
        : "+f"(d[0]), "+f"(d[1]), "+f"(d[2]), "+f"(d[3])
        : "r"(a[0]), "r"(a[1]), "r"(a[2]), "r"(a[3]), "r"(b0), "r"(b1));
}

// ───────────── pre-kernel: combine (64 blocks) | bc (512 blocks) ─────────────
__global__ __launch_bounds__(256)
void pre_kernel(const float* __restrict__ Wv, const float* __restrict__ Wo,
                const float* __restrict__ bv, const float* __restrict__ bo)
{
    const int b = blockIdx.x;
    const int tid = threadIdx.x;

    if (b < 64) {
        // ---- combine role: 64x64 tile of Wc = Wv@Wo, 4x4 microtile ----
        __shared__ float As[32][68];   // As[k][m]
        __shared__ float Bs[32][68];   // Bs[k][n]
        const int kb0 = (b >> 3) * 64;   // Wc row block (k of WcT layout)
        const int nb0 = (b & 7) * 64;    // Wc col block (n)
        const int ty = (tid >> 4) * 4;
        const int tx = (tid & 15) * 4;

        float acc[4][4] = {};
        for (int k0 = 0; k0 < D; k0 += 32) {
            #pragma unroll
            for (int u = 0; u < 2; u++) {
                const int idx = tid + u * 256;       // 0..511
                const int r = idx >> 3, c = (idx & 7) * 4;  // A: 64 rows x 8 f4
                float4 va = *reinterpret_cast<const float4*>(
                    &Wv[(size_t)(kb0 + r) * D + k0 + c]);
                As[c + 0][r] = va.x; As[c + 1][r] = va.y;
                As[c + 2][r] = va.z; As[c + 3][r] = va.w;
            }
            #pragma unroll
            for (int u = 0; u < 2; u++) {
                const int idx = tid + u * 256;
                const int r = idx >> 4, c = (idx & 15) * 4; // B: 32 rows x 16 f4
                *reinterpret_cast<float4*>(&Bs[r][c]) =
                    *reinterpret_cast<const float4*>(
                        &Wo[(size_t)(k0 + r) * D + nb0 + c]);
            }
            __syncthreads();
            #pragma unroll
            for (int k = 0; k < 32; k++) {
                float4 ra = *reinterpret_cast<const float4*>(&As[k][ty]);
                float4 rb = *reinterpret_cast<const float4*>(&Bs[k][tx]);
                const float a4[4] = {ra.x, ra.y, ra.z, ra.w};
                const float b4[4] = {rb.x, rb.y, rb.z, rb.w};
                #pragma unroll
                for (int i = 0; i < 4; i++)
                    #pragma unroll
                    for (int j = 0; j < 4; j++)
                        acc[i][j] += a4[i] * b4[j];
            }
            __syncthreads();
        }
        #pragma unroll
        for (int i = 0; i < 4; i++)
            #pragma unroll
            for (int j = 0; j < 4; j++) {
                const int k = kb0 + ty + i;
                const int n = nb0 + tx + j;
                g_Bhi[(size_t)n * D + k] = __float2half_rn(acc[i][j]);
            }
        return;
    }

    // ---- bc role ----
    {
        __shared__ float red[8];
        const int n = b - 64;
        float s = 0.f;
        #pragma unroll
        for (int j = tid; j < D; j += 256) s += bv[j] * Wo[(size_t)j * D + n];
        #pragma unroll
        for (int o = 16; o > 0; o >>= 1) s += __shfl_down_sync(0xFFFFFFFF, s, o);
        if ((tid & 31) == 0) red[tid >> 5] = s;
        __syncthreads();
        if (tid == 0) {
            float t = 0.f;
            #pragma unroll
            for (int w = 0; w < 8; w++) t += red[w];
            g_bc[n] = t + bo[n];
        }
    }
}

// ───────────── main GEMM: fp32 A inline-converted, fp16 mma.sync ─────────────
// CTA 128x128, BK=32. A: 2-stage LDG->cvt->STS reg double-buffer.
// B: 4-stage cp.async. ONE barrier per k-iter. 8 warps, 64x32 warp tile, 2 CTA/SM.
#define BM 128
#define BN 128
#define BKK 32
#define ROWB 80                        // smem row stride bytes
#define A_TILE (128 * ROWB)            // 10240 B
#define B_TILE (128 * ROWB)            // 10240 B
#define A_STAGES 2
#define B_STAGES 4
#define B_BASE (A_STAGES * A_TILE)
#define SMEM_TOTAL (A_STAGES * A_TILE + B_STAGES * B_TILE)   // 61440 B

__global__ __launch_bounds__(256, 2)
void mma_kernel(const float* __restrict__ x,
                const __half* __restrict__ Bhi,
                const float* __restrict__ bc, float* __restrict__ out)
{
    extern __shared__ char smem[];
    const uint32_t sb = smem_u32(smem);
    const int tid = threadIdx.x;
    const int lane = tid & 31;
    const int wid = tid >> 5;
    const int n0 = blockIdx.x * BN;   // n fast: 4 CTAs share an A tile
    const int m0 = blockIdx.y * BM;
    const int wm = (wid >> 2) * 64;
    const int wn = (wid & 3) * 32;

    const int ar = tid >> 3;          // 0..31 (base row)
    const int ac = tid & 7;           // float4 column (0..7)

    float4 areg[4];

    auto lda = [&](int kb) {
        const int k0 = kb * BKK;
        #pragma unroll
        for (int u = 0; u < 4; u++) {
            const int r = ar + u * 32;
            areg[u] = __ldg(reinterpret_cast<const float4*>(
                &x[(size_t)(m0 + r) * D + k0 + ac * 4]));
        }
    };
    auto sta = [&](int s) {
        char* base = smem + s * A_TILE;
        #pragma unroll
        for (int u = 0; u < 4; u++) {
            const int r = ar + u * 32;
            __half2 h0 = __floats2half2_rn(areg[u].x, areg[u].y);
            __half2 h1 = __floats2half2_rn(areg[u].z, areg[u].w);
            uint2 v;
            v.x = *reinterpret_cast<uint32_t*>(&h0);
            v.y = *reinterpret_cast<uint32_t*>(&h1);
            *reinterpret_cast<uint2*>(base + r * ROWB + ac * 8) = v;
        }
    };
    auto ldb = [&](int kb, int s) {
        const uint32_t base = sb + B_BASE + (uint32_t)s * B_TILE;
        const int k0 = kb * BKK;
        #pragma unroll
        for (int u = 0; u < 2; u++) {
            const int ch = tid + u * 256;        // 0..511
            const int r = ch >> 2, c = ch & 3;   // 128 rows x 4 16B-chunks
            cp16(base + r * ROWB + c * 16,
                 Bhi + (size_t)(n0 + r) * D + k0 + c * 8);
        }
    };

    float acc[4][4][4] = {};
    const int NKB = D / BKK;   // 16

    // prologue: B stages 0..3, A stage 0 + regs hold A(1)
    ldb(0, 0); cp_commit();
    ldb(1, 1); cp_commit();
    ldb(2, 2); cp_commit();
    ldb(3, 3); cp_commit();
    lda(0); sta(0);
    lda(1);

    for (int kb = 0; kb < NKB; kb++) {
        // wait for B(kb): allowed pending groups = min(3, NKB-1-kb)
        if (kb <= NKB - 4)      cp_wait<3>();
        else if (kb == NKB - 3) cp_wait<2>();
        else if (kb == NKB - 2) cp_wait<1>();
        else                    cp_wait<0>();
        __syncthreads();   // single barrier per iteration

        const uint32_t baseA = sb + (uint32_t)(kb & 1) * A_TILE;
        const uint32_t baseB = sb + B_BASE + (uint32_t)(kb & 3) * B_TILE;
        #pragma unroll
        for (int ks = 0; ks < 2; ks++) {
            uint32_t a[4][4];
            #pragma unroll
            for (int mi = 0; mi < 4; mi++) {
                uint32_t ra = baseA + (uint32_t)(wm + mi * 16 + (lane & 15)) * ROWB
                            + ks * 32 + ((lane >> 4) << 4);
                ldsm_x4(a[mi], ra);
            }
            uint32_t bh[2][4];
            #pragma unroll
            for (int bi = 0; bi < 2; bi++) {
                const int nl = wn + bi * 16 + (lane & 7) + ((lane >> 4) << 3);
                uint32_t rb = baseB + (uint32_t)nl * ROWB
                            + ks * 32 + (((lane >> 3) & 1) << 4);
                ldsm_x4(bh[bi], rb);
            }
            #pragma unroll
            for (int mi = 0; mi < 4; mi++)
                #pragma unroll
                for (int ni = 0; ni < 4; ni++) {
                    const int bi = ni >> 1, p = (ni & 1) * 2;
                    mma_f16(acc[mi][ni], a[mi], bh[bi][p], bh[bi][p + 1]);
                }
        }

        // prefetch (no barrier needed: targets last read >=1 barrier ago)
        if (kb + 1 < NKB) sta((kb + 1) & 1);           // A(kb+1) regs -> smem
        if (kb + 2 < NKB) lda(kb + 2);                 // A(kb+2) -> regs
        if (kb + 4 < NKB) ldb(kb + 4, (kb + 4) & 3);   // B(kb+4) -> smem
        cp_commit();                                   // uniform group counting
    }

    // epilogue: fp32 stores + bias
    #pragma unroll
    for (int mi = 0; mi < 4; mi++) {
        const int r = m0 + wm + mi * 16 + (lane >> 2);
        #pragma unroll
        for (int ni = 0; ni < 4; ni++) {
            const int c = n0 + wn + ni * 8 + (lane & 3) * 2;
            float2 bv = *reinterpret_cast<const float2*>(&bc[c]);
            float2 v0 = make_float2(acc[mi][ni][0] + bv.x, acc[mi][ni][1] + bv.y);
            float2 v1 = make_float2(acc[mi][ni][2] + bv.x, acc[mi][ni][3] + bv.y);
            *reinterpret_cast<float2*>(&out[(size_t)r * D + c]) = v0;
            *reinterpret_cast<float2*>(&out[(size_t)(r + 8) * D + c]) = v1;
        }
    }
}

// ───────────────────────── host ─────────────────────────
extern "C" void kernel_launch(void* const* d_in, const int* in_sizes, int n_in,
                              void* d_out, int out_size)
{
    // order: x, H, W, Wq, bq, Wk, bk, Wv, bv, Wo, bo, Woff1, boff1, Woff2, boff2
    const float* x  = (const float*)d_in[0];
    const float* Wv = (const float*)d_in[7];
    const float* bv = (const float*)d_in[8];
    const float* Wo = (const float*)d_in[9];
    const float* bo = (const float*)d_in[10];
    float* out = (float*)d_out;

    const int M = in_sizes[0] / D;   // 16384 tokens

    __half* bhi;
    float* bc;
    cudaGetSymbolAddress((void**)&bhi, g_Bhi);
    cudaGetSymbolAddress((void**)&bc,  g_bc);

    static bool attr_set = false;
    if (!attr_set) {
        cudaFuncSetAttribute(mma_kernel,
                             cudaFuncAttributeMaxDynamicSharedMemorySize, SMEM_TOTAL);
        attr_set = true;
    }

    pre_kernel<<<64 + D, 256>>>(Wv, Wo, bv, bo);
    mma_kernel<<<dim3(D / BN, M / BM), 256, SMEM_TOTAL>>>(x, bhi, bc, out);
}

// round 9
// speedup vs baseline: 1.6457x; 1.0514x over previous
#include <cuda_runtime.h>
#include <cuda_fp16.h>
#include <cstdint>

// out = x @ (Wv@Wo) + (bv@Wo + bo)   (algebraic collapse, validated r1)
// Single-pass fp16 GEMM, inline fp32->fp16 A conversion. rel_err 2.94e-4 measured.

#define D 512

__device__ __half g_Bhi[D * D];   // WcT fp16  [n][k]
__device__ float g_bc[D];

// ───────────────────────── helpers ─────────────────────────
__device__ __forceinline__ uint32_t smem_u32(const void* p) {
    uint32_t a;
    asm("{ .reg .u64 t; cvta.to.shared.u64 t, %1; cvt.u32.u64 %0, t; }"
        : "=r"(a) : "l"(p));
    return a;
}
__device__ __forceinline__ void cp16(uint32_t dst, const void* src) {
    asm volatile("cp.async.cg.shared.global [%0], [%1], 16;"
                 :: "r"(dst), "l"(src) : "memory");
}
__device__ __forceinline__ void cp_commit() {
    asm volatile("cp.async.commit_group;" ::: "memory");
}
template <int N>
__device__ __forceinline__ void cp_wait() {
    asm volatile("cp.async.wait_group %0;" :: "n"(N) : "memory");
}
__device__ __forceinline__ void ldsm_x4(uint32_t (&r)[4], uint32_t addr) {
    asm volatile("ldmatrix.sync.aligned.m8n8.x4.shared.b16 {%0,%1,%2,%3}, [%4];"
                 : "=r"(r[0]), "=r"(r[1]), "=r"(r[2]), "=r"(r[3]) : "r"(addr));
}
__device__ __forceinline__ void mma_f16(float (&d)[4], const uint32_t (&a)[4],
                                        uint32_t b0, uint32_t b1) {
    asm volatile(
        "mma.sync.aligned.m16n8k16.row.col.f32.f16.f16.f32 "
        "{%0,%1,%2,%3}, {%4,%5,%6,%7}, {%8,%9}, {%0,%1,%2,%3};"
        : "+f"(d[0]), "+f"(d[1]), "+f"(d[2]), "+f"(d[3])
        : "r"(a[0]), "r"(a[1]), "r"(a[2]), "r"(a[3]), "r"(b0), "r"(b1));
}

// ───────────── pre-kernel: combine (64 blocks) | bc (8 blocks) ─────────────
__global__ __launch_bounds__(256)
void pre_kernel(const float* __restrict__ Wv, const float* __restrict__ Wo,
                const float* __restrict__ bv, const float* __restrict__ bo)
{
    const int b = blockIdx.x;
    const int tid = threadIdx.x;

    if (b < 64) {
        // ---- combine role: 64x64 tile of Wc = Wv@Wo, 4x4 microtile ----
        __shared__ float As[32][68];   // As[k][m]
        __shared__ float Bs[32][68];   // Bs[k][n]
        const int kb0 = (b >> 3) * 64;
        const int nb0 = (b & 7) * 64;
        const int ty = (tid >> 4) * 4;
        const int tx = (tid & 15) * 4;

        float acc[4][4] = {};
        for (int k0 = 0; k0 < D; k0 += 32) {
            #pragma unroll
            for (int u = 0; u < 2; u++) {
                const int idx = tid + u * 256;
                const int r = idx >> 3, c = (idx & 7) * 4;  // A: 64 rows x 8 f4
                float4 va = *reinterpret_cast<const float4*>(
                    &Wv[(size_t)(kb0 + r) * D + k0 + c]);
                As[c + 0][r] = va.x; As[c + 1][r] = va.y;
                As[c + 2][r] = va.z; As[c + 3][r] = va.w;
            }
            #pragma unroll
            for (int u = 0; u < 2; u++) {
                const int idx = tid + u * 256;
                const int r = idx >> 4, c = (idx & 15) * 4; // B: 32 rows x 16 f4
                *reinterpret_cast<float4*>(&Bs[r][c]) =
                    *reinterpret_cast<const float4*>(
                        &Wo[(size_t)(k0 + r) * D + nb0 + c]);
            }
            __syncthreads();
            #pragma unroll
            for (int k = 0; k < 32; k++) {
                float4 ra = *reinterpret_cast<const float4*>(&As[k][ty]);
                float4 rb = *reinterpret_cast<const float4*>(&Bs[k][tx]);
                const float a4[4] = {ra.x, ra.y, ra.z, ra.w};
                const float b4[4] = {rb.x, rb.y, rb.z, rb.w};
                #pragma unroll
                for (int i = 0; i < 4; i++)
                    #pragma unroll
                    for (int j = 0; j < 4; j++)
                        acc[i][j] += a4[i] * b4[j];
            }
            __syncthreads();
        }
        #pragma unroll
        for (int i = 0; i < 4; i++)
            #pragma unroll
            for (int j = 0; j < 4; j++) {
                const int k = kb0 + ty + i;
                const int n = nb0 + tx + j;
                g_Bhi[(size_t)n * D + k] = __float2half_rn(acc[i][j]);
            }
        return;
    }

    // ---- bc role: 8 blocks x 64 n-cols, coalesced row reads ----
    {
        __shared__ float red[4][64];
        const int n0 = (b - 64) * 64;
        const int nn = tid & 63;
        const int kk = tid >> 6;
        float s = 0.f;
        #pragma unroll 16
        for (int k = kk; k < D; k += 4)
            s += bv[k] * Wo[(size_t)k * D + n0 + nn];
        red[kk][nn] = s;
        __syncthreads();
        if (tid < 64)
            g_bc[n0 + tid] = red[0][tid] + red[1][tid] + red[2][tid] + red[3][tid]
                           + bo[n0 + tid];
    }
}

// ───────────── main GEMM: fp32 A inline-converted, fp16 mma.sync ─────────────
// CTA 128x128, BK=32. A: 2-stage LDG->cvt->STS reg buffer. B: 4-stage cp.async,
// prefetch distance 3. Dependency-safe order: sta -> lda -> ldb -> MMA.
#define BM 128
#define BN 128
#define BKK 32
#define ROWB 80
#define A_TILE (128 * ROWB)
#define B_TILE (128 * ROWB)
#define A_STAGES 2
#define B_STAGES 4
#define B_BASE (A_STAGES * A_TILE)
#define SMEM_TOTAL (A_STAGES * A_TILE + B_STAGES * B_TILE)   // 61440 B
#define NKB (D / BKK)   // 16

__global__ __launch_bounds__(256, 2)
void mma_kernel(const float* __restrict__ x,
                const __half* __restrict__ Bhi,
                const float* __restrict__ bc, float* __restrict__ out)
{
    extern __shared__ char smem[];
    const uint32_t sb = smem_u32(smem);
    const int tid = threadIdx.x;
    const int lane = tid & 31;
    const int wid = tid >> 5;
    const int n0 = blockIdx.x * BN;   // n fast: 4 CTAs share an A tile
    const int m0 = blockIdx.y * BM;
    const int wm = (wid >> 2) * 64;
    const int wn = (wid & 3) * 32;

    const int ar = tid >> 3;          // 0..31
    const int ac = tid & 7;           // float4 column

    float4 areg[4];

    auto lda = [&](int kb) {
        const int k0 = kb * BKK;
        #pragma unroll
        for (int u = 0; u < 4; u++) {
            const int r = ar + u * 32;
            areg[u] = __ldg(reinterpret_cast<const float4*>(
                &x[(size_t)(m0 + r) * D + k0 + ac * 4]));
        }
    };
    auto sta = [&](int s) {
        char* base = smem + s * A_TILE;
        #pragma unroll
        for (int u = 0; u < 4; u++) {
            const int r = ar + u * 32;
            __half2 h0 = __floats2half2_rn(areg[u].x, areg[u].y);
            __half2 h1 = __floats2half2_rn(areg[u].z, areg[u].w);
            uint2 v;
            v.x = *reinterpret_cast<uint32_t*>(&h0);
            v.y = *reinterpret_cast<uint32_t*>(&h1);
            *reinterpret_cast<uint2*>(base + r * ROWB + ac * 8) = v;
        }
    };
    auto ldb = [&](int kb, int s) {
        const uint32_t base = sb + B_BASE + (uint32_t)s * B_TILE;
        const int k0 = kb * BKK;
        #pragma unroll
        for (int u = 0; u < 2; u++) {
            const int ch = tid + u * 256;
            const int r = ch >> 2, c = ch & 3;
            cp16(base + r * ROWB + c * 16,
                 Bhi + (size_t)(n0 + r) * D + k0 + c * 8);
        }
    };

    float acc[4][4][4] = {};

    // prologue: B stages 0..2 (distance 3), A stage 0, regs hold A(1)
    ldb(0, 0); cp_commit();
    ldb(1, 1); cp_commit();
    ldb(2, 2); cp_commit();
    lda(0); sta(0);
    lda(1);

    #pragma unroll
    for (int kb = 0; kb < NKB; kb++) {
        // need B(kb) complete; outstanding after: B(kb+1), B(kb+2)
        if (kb <= NKB - 3)      cp_wait<2>();
        else if (kb == NKB - 2) cp_wait<1>();
        else                    cp_wait<0>();
        __syncthreads();

        // dependency-safe front-loading:
        // 1) consume areg (A(kb+1)) into smem; target stage last read in iter kb-1
        if (kb + 1 < NKB) sta((kb + 1) & 1);
        // 2) refill areg with A(kb+2)
        if (kb + 2 < NKB) lda(kb + 2);
        // 3) B(kb+3) -> stage (kb+3)&3 = (kb-1)&3, last read before this barrier
        if (kb + 3 < NKB) ldb(kb + 3, (kb + 3) & 3);
        cp_commit();

        const uint32_t baseA = sb + (uint32_t)(kb & 1) * A_TILE;
        const uint32_t baseB = sb + B_BASE + (uint32_t)(kb & 3) * B_TILE;
        #pragma unroll
        for (int ks = 0; ks < 2; ks++) {
            uint32_t a[4][4];
            #pragma unroll
            for (int mi = 0; mi < 4; mi++) {
                uint32_t ra = baseA + (uint32_t)(wm + mi * 16 + (lane & 15)) * ROWB
                            + ks * 32 + ((lane >> 4) << 4);
                ldsm_x4(a[mi], ra);
            }
            uint32_t bh[2][4];
            #pragma unroll
            for (int bi = 0; bi < 2; bi++) {
                const int nl = wn + bi * 16 + (lane & 7) + ((lane >> 4) << 3);
                uint32_t rb = baseB + (uint32_t)nl * ROWB
                            + ks * 32 + (((lane >> 3) & 1) << 4);
                ldsm_x4(bh[bi], rb);
            }
            #pragma unroll
            for (int mi = 0; mi < 4; mi++)
                #pragma unroll
                for (int ni = 0; ni < 4; ni++) {
                    const int bi = ni >> 1, p = (ni & 1) * 2;
                    mma_f16(acc[mi][ni], a[mi], bh[bi][p], bh[bi][p + 1]);
                }
        }
    }

    // epilogue: fp32 stores + bias
    #pragma unroll
    for (int mi = 0; mi < 4; mi++) {
        const int r = m0 + wm + mi * 16 + (lane >> 2);
        #pragma unroll
        for (int ni = 0; ni < 4; ni++) {
            const int c = n0 + wn + ni * 8 + (lane & 3) * 2;
            float2 bv = *reinterpret_cast<const float2*>(&bc[c]);
            float2 v0 = make_float2(acc[mi][ni][0] + bv.x, acc[mi][ni][1] + bv.y);
            float2 v1 = make_float2(acc[mi][ni][2] + bv.x, acc[mi][ni][3] + bv.y);
            *reinterpret_cast<float2*>(&out[(size_t)r * D + c]) = v0;
            *reinterpret_cast<float2*>(&out[(size_t)(r + 8) * D + c]) = v1;
        }
    }
}

// ───────────────────────── host ─────────────────────────
extern "C" void kernel_launch(void* const* d_in, const int* in_sizes, int n_in,
                              void* d_out, int out_size)
{
    // order: x, H, W, Wq, bq, Wk, bk, Wv, bv, Wo, bo, Woff1, boff1, Woff2, boff2
    const float* x  = (const float*)d_in[0];
    const float* Wv = (const float*)d_in[7];
    const float* bv = (const float*)d_in[8];
    const float* Wo = (const float*)d_in[9];
    const float* bo = (const float*)d_in[10];
    float* out = (float*)d_out;

    const int M = in_sizes[0] / D;   // 16384 tokens

    __half* bhi;
    float* bc;
    cudaGetSymbolAddress((void**)&bhi, g_Bhi);
    cudaGetSymbolAddress((void**)&bc,  g_bc);

    static bool attr_set = false;
    if (!attr_set) {
        cudaFuncSetAttribute(mma_kernel,
                             cudaFuncAttributeMaxDynamicSharedMemorySize, SMEM_TOTAL);
        attr_set = true;
    }

    pre_kernel<<<64 + 8, 256>>>(Wv, Wo, bv, bo);
    mma_kernel<<<dim3(D / BN, M / BM), 256, SMEM_TOTAL>>>(x, bhi, bc, out);
}